// round 1
// baseline (speedup 1.0000x reference)
#include <cuda_runtime.h>

#define NTOT 8192
#define BB   8
#define NBAT 1024
#define KK   9
#define CC   32
#define CMID 128
#define MM   9216        // NBAT*KK, per batch
#define MSPLIT 4
#define MCHUNK 2304      // MM / MSPLIT
#define MTILE  64
#define NTILES 36        // MCHUNK / MTILE

// ---------------- scratch (device globals; no allocation anywhere) ----------
__device__ float g_convw[BB * MM * CC];     // (b*9216+m, c)
__device__ float g_convpos[BB * MM * 2];    // (b*9216+m, 2)
__device__ float g_part[MSPLIT * NTOT * CC];
__device__ float g_x[NTOT * CC];            // leaky(sampled)
__device__ float g_xn[NTOT * CC];           // batchnorm(x)+weights
__device__ float g_h[NTOT * CMID];          // leaky(xn@W1+b1)
__device__ float g_sx[CC], g_sx2[CC], g_sh[CMID], g_sh2[CMID];
__device__ float g_xscale[CC], g_xshift[CC], g_hscale[CMID], g_hshift[CMID];

// ---------------- K1: conv_w einsum + conv_pos + zero stats -----------------
// grid 8192 (one block per n), 288 threads = (k=tid/32, d=tid%32)
__global__ void k_prep(const float* __restrict__ pos,
                       const float* __restrict__ wts,
                       const float* __restrict__ kpos,
                       const float* __restrict__ kw) {
    __shared__ float sw[CC];
    int n = blockIdx.x;
    int tid = threadIdx.x;
    if (tid < CC) sw[tid] = wts[n * CC + tid];
    if (n == 0) {  // re-zero stats every replay
        if (tid < CC)   { g_sx[tid] = 0.f; g_sx2[tid] = 0.f; }
        if (tid < CMID) { g_sh[tid] = 0.f; g_sh2[tid] = 0.f; }
    }
    __syncthreads();
    int k = tid >> 5, d = tid & 31;
    const float* kwk = kw + k * CC * CC + d;   // kw[k][c][d], stride 32 over c
    float a = 0.f;
    #pragma unroll
    for (int c = 0; c < CC; c++) a = fmaf(sw[c], kwk[c * CC], a);
    g_convw[(size_t)n * (KK * CC) + tid] = a;  // row n*9+k, col d
    if (tid < KK * 2) {
        int kk = tid >> 1, j = tid & 1;
        g_convpos[(n * KK + kk) * 2 + j] = pos[n * 2 + j] + kpos[kk * 2 + j];
    }
}

// ---------------- K2: main Kmat @ conv_w -----------------------------------
// grid 128 = b(8) x nchunk(4) x msplit(4); 256 threads, one n per thread
__global__ void __launch_bounds__(256) k_main(const float* __restrict__ pos) {
    __shared__ float  s_cw[MTILE * CC];   // 8 KB
    __shared__ float2 s_cp[MTILE];
    int blk = blockIdx.x;
    int b  = blk >> 4;
    int nc = (blk >> 2) & 3;
    int ms = blk & 3;
    int tid = threadIdx.x;
    int n = b * NBAT + nc * 256 + tid;
    float px = pos[n * 2 + 0];
    float py = pos[n * 2 + 1];
    float acc[CC];
    #pragma unroll
    for (int c = 0; c < CC; c++) acc[c] = 0.f;

    int mbase = b * MM + ms * MCHUNK;
    for (int t = 0; t < NTILES; t++) {
        int m0 = mbase + t * MTILE;
        const float4* src = (const float4*)(g_convw + (size_t)m0 * CC);
        float4* dst = (float4*)s_cw;
        dst[tid]       = src[tid];
        dst[tid + 256] = src[tid + 256];
        if (tid < MTILE) s_cp[tid] = ((const float2*)g_convpos)[m0 + tid];
        __syncthreads();
        #pragma unroll 2
        for (int j = 0; j < MTILE; j++) {
            float2 cp = s_cp[j];
            float dx = px - cp.x, dy = py - cp.y;
            float d2 = fmaf(dy, dy, dx * dx);
            float w = __expf(-2.0f * d2);
            const float4* cw = (const float4*)(s_cw + j * CC);
            #pragma unroll
            for (int q = 0; q < 8; q++) {
                float4 v = cw[q];
                acc[4 * q + 0] = fmaf(w, v.x, acc[4 * q + 0]);
                acc[4 * q + 1] = fmaf(w, v.y, acc[4 * q + 1]);
                acc[4 * q + 2] = fmaf(w, v.z, acc[4 * q + 2]);
                acc[4 * q + 3] = fmaf(w, v.w, acc[4 * q + 3]);
            }
        }
        __syncthreads();
    }
    float4* outp = (float4*)(g_part + ((size_t)ms * NTOT + n) * CC);
    #pragma unroll
    for (int q = 0; q < 8; q++)
        outp[q] = make_float4(acc[4*q], acc[4*q+1], acc[4*q+2], acc[4*q+3]);
}

// ---------------- K3: sum partials, leaky, BN stats for x -------------------
// grid 128, 256 threads; 64 rows/block; tid = (rs=tid>>5, c=tid&31)
__global__ void k_x_stats() {
    __shared__ float red[256];
    int n0 = blockIdx.x * 64;
    int tid = threadIdx.x;
    int c = tid & 31, rs = tid >> 5;
    float sx = 0.f, sx2 = 0.f;
    #pragma unroll
    for (int i = 0; i < 8; i++) {
        int n = n0 + rs + 8 * i;
        size_t o = (size_t)n * CC + c;
        float v = g_part[o] + g_part[NTOT*CC + o] + g_part[2*NTOT*CC + o] + g_part[3*NTOT*CC + o];
        float x = v >= 0.f ? v : 0.01f * v;
        g_x[o] = x;
        sx += x; sx2 += x * x;
    }
    red[tid] = sx; __syncthreads();
    if (rs == 0) {
        float s = 0.f;
        #pragma unroll
        for (int j = 0; j < 8; j++) s += red[c + 32 * j];
        atomicAdd(&g_sx[c], s);
    }
    __syncthreads(); red[tid] = sx2; __syncthreads();
    if (rs == 0) {
        float s = 0.f;
        #pragma unroll
        for (int j = 0; j < 8; j++) s += red[c + 32 * j];
        atomicAdd(&g_sx2[c], s);
    }
}

__global__ void k_xfin(const float* __restrict__ gamma, const float* __restrict__ beta) {
    int c = threadIdx.x;
    float mu = g_sx[c] / (float)NTOT;
    float var = g_sx2[c] / (float)NTOT - mu * mu;
    float rs = rsqrtf(var + 1e-5f);
    g_xscale[c] = gamma[c] * rs;
    g_xshift[c] = beta[c] - gamma[c] * rs * mu;
}

// ---------------- K5: xn, h = leaky(xn@W1+b1), BN stats for h ---------------
// grid 256, 256 threads; 32 rows/block
__global__ void __launch_bounds__(256) k_h(const float* __restrict__ wts,
                                           const float* __restrict__ W1,
                                           const float* __restrict__ b1) {
    __shared__ float sxn[32 * CC];      // 4 KB
    __shared__ float sW1[CC * CMID];    // 16 KB
    __shared__ float red[256];
    int n0 = blockIdx.x * 32;
    int tid = threadIdx.x;
    #pragma unroll
    for (int i = 0; i < 4; i++) {
        int idx = tid + 256 * i;
        int r = idx >> 5, c = idx & 31;
        size_t o = (size_t)(n0 + r) * CC + c;
        float v = g_xscale[c] * g_x[o] + g_xshift[c] + wts[o];
        sxn[idx] = v;
        g_xn[o] = v;
    }
    #pragma unroll
    for (int i = 0; i < 16; i++) sW1[tid + 256 * i] = W1[tid + 256 * i];
    __syncthreads();
    int c = tid & 127, rg = tid >> 7;  // rg 0..1
    float bc = b1[c];
    float sh = 0.f, sh2 = 0.f;
    for (int i = 0; i < 16; i++) {
        int r = rg + 2 * i;
        float a = bc;
        #pragma unroll
        for (int cin = 0; cin < CC; cin++)
            a = fmaf(sxn[r * CC + cin], sW1[cin * CMID + c], a);
        float h = a >= 0.f ? a : 0.01f * a;
        g_h[(size_t)(n0 + r) * CMID + c] = h;
        sh += h; sh2 += h * h;
    }
    red[tid] = sh; __syncthreads();
    if (rg == 0) atomicAdd(&g_sh[c], red[c] + red[c + 128]);
    __syncthreads(); red[tid] = sh2; __syncthreads();
    if (rg == 0) atomicAdd(&g_sh2[c], red[c] + red[c + 128]);
}

__global__ void k_hfin(const float* __restrict__ gamma, const float* __restrict__ beta) {
    int c = threadIdx.x;
    float mu = g_sh[c] / (float)NTOT;
    float var = g_sh2[c] / (float)NTOT - mu * mu;
    float rs = rsqrtf(var + 1e-5f);
    g_hscale[c] = gamma[c] * rs;
    g_hshift[c] = beta[c] - gamma[c] * rs * mu;
}

// ---------------- K6: mlp_out = hn@W2+b2, write both outputs ----------------
// grid 1024, 256 threads = 8 warps, one row per warp
__global__ void __launch_bounds__(256) k_final(const float* __restrict__ pos,
                                               const float* __restrict__ W2,
                                               const float* __restrict__ b2,
                                               float* __restrict__ out) {
    __shared__ float sW2[CMID * 34];   // 17.4 KB
    __shared__ float sb2[34];
    __shared__ float shn[8][CMID];
    int tid = threadIdx.x;
    for (int i = tid; i < CMID * 34; i += 256) sW2[i] = W2[i];
    if (tid < 34) sb2[tid] = b2[tid];
    int w = tid >> 5, lane = tid & 31;
    int n = blockIdx.x * 8 + w;
    #pragma unroll
    for (int i = 0; i < 4; i++) {
        int cin = lane + 32 * i;
        float hv = g_h[(size_t)n * CMID + cin];
        shn[w][cin] = g_hscale[cin] * hv + g_hshift[cin];
    }
    __syncthreads();
    float acc1 = sb2[lane];
    #pragma unroll 8
    for (int cin = 0; cin < CMID; cin++)
        acc1 = fmaf(shn[w][cin], sW2[cin * 34 + lane], acc1);
    float* out_pos = out;               // N*2
    float* out_w   = out + NTOT * 2;    // N*32
    if (lane < 2) {
        out_pos[n * 2 + lane] = pos[n * 2 + lane] + acc1;
        float acc2 = sb2[32 + lane];
        #pragma unroll 8
        for (int cin = 0; cin < CMID; cin++)
            acc2 = fmaf(shn[w][cin], sW2[cin * 34 + 32 + lane], acc2);
        out_w[n * CC + 30 + lane] = g_xn[(size_t)n * CC + 30 + lane] + acc2;
    } else {
        out_w[n * CC + lane - 2] = g_xn[(size_t)n * CC + lane - 2] + acc1;
    }
}

// ---------------- launch ----------------------------------------------------
extern "C" void kernel_launch(void* const* d_in, const int* in_sizes, int n_in,
                              void* d_out, int out_size) {
    const float* positions = (const float*)d_in[0];
    const float* weights   = (const float*)d_in[1];
    // d_in[2] = batch (all NB, unused; shapes are static)
    const float* kpos = (const float*)d_in[3];
    const float* kw   = (const float*)d_in[4];
    const float* cng  = (const float*)d_in[5];
    const float* cnb  = (const float*)d_in[6];
    const float* W1   = (const float*)d_in[7];
    const float* b1   = (const float*)d_in[8];
    const float* bng  = (const float*)d_in[9];
    const float* bnb  = (const float*)d_in[10];
    const float* W2   = (const float*)d_in[11];
    const float* b2   = (const float*)d_in[12];
    float* out = (float*)d_out;

    k_prep<<<NTOT, 288>>>(positions, weights, kpos, kw);
    k_main<<<128, 256>>>(positions);
    k_x_stats<<<128, 256>>>();
    k_xfin<<<1, CC>>>(cng, cnb);
    k_h<<<256, 256>>>(weights, W1, b1);
    k_hfin<<<1, CMID>>>(bng, bnb);
    k_final<<<1024, 256>>>(positions, W2, b2, out);
}

// round 2
// speedup vs baseline: 1.2875x; 1.2875x over previous
#include <cuda_runtime.h>

#define NTOT 8192
#define BB   8
#define NBAT 1024
#define KK   9
#define CC   32
#define CMID 128
#define MM   9216        // NBAT*KK, per batch
#define MSPLIT 9
#define MCHUNK 1024      // MM / MSPLIT
#define MTILE  64
#define NTILES 16        // MCHUNK / MTILE

// ---------------- scratch (device globals; no allocation anywhere) ----------
__device__ float g_convw[BB * MM * CC];     // (b*9216+m, c)
__device__ float g_convpos[BB * MM * 2];    // (b*9216+m, 2)
__device__ float g_part[MSPLIT * NTOT * CC];
__device__ float g_x[NTOT * CC];            // leaky(sampled)
__device__ float g_xn[NTOT * CC];           // batchnorm(x)+weights
__device__ float g_h[NTOT * CMID];          // leaky(xn@W1+b1)
__device__ float g_sx[CC], g_sx2[CC], g_sh[CMID], g_sh2[CMID];

// ---------------- f32x2 helpers ---------------------------------------------
__device__ __forceinline__ void ffma2(unsigned long long& d,
                                      unsigned long long a,
                                      unsigned long long b) {
    asm("fma.rn.f32x2 %0, %1, %2, %0;" : "+l"(d) : "l"(a), "l"(b));
}
__device__ __forceinline__ unsigned long long pack2(float x) {
    unsigned long long r;
    asm("mov.b64 %0, {%1, %2};" : "=l"(r) : "f"(x), "f"(x));
    return r;
}
__device__ __forceinline__ float ex2(float x) {
    float y;
    asm("ex2.approx.f32 %0, %1;" : "=f"(y) : "f"(x));
    return y;
}

// ---------------- K1: conv_w einsum + conv_pos + zero stats -----------------
// grid 128 (64 n per block), 288 threads = (k=tid/32, d=tid%32)
__global__ void __launch_bounds__(288) k_prep(const float* __restrict__ pos,
                                              const float* __restrict__ wts,
                                              const float* __restrict__ kpos,
                                              const float* __restrict__ kw) {
    __shared__ __align__(16) float sw[64 * CC];   // 8 KB
    __shared__ float sp[64 * 2];
    __shared__ float skp[KK * 2];
    int tid = threadIdx.x;
    int n0 = blockIdx.x * 64;
    if (blockIdx.x == 0) {   // re-zero stats every replay
        if (tid < CC)   { g_sx[tid] = 0.f; g_sx2[tid] = 0.f; }
        if (tid < CMID) { g_sh[tid] = 0.f; g_sh2[tid] = 0.f; }
    }
    for (int i = tid; i < 64 * CC; i += 288) sw[i] = wts[n0 * CC + i];
    for (int i = tid; i < 128; i += 288)     sp[i] = pos[n0 * 2 + i];
    if (tid < KK * 2) skp[tid] = kpos[tid];
    int k = tid / 32, d = tid % 32;
    float kr[CC];
    #pragma unroll
    for (int c = 0; c < CC; c++) kr[c] = kw[(k * CC + c) * CC + d];
    __syncthreads();
    for (int n = 0; n < 64; n++) {
        const float4* swr = (const float4*)(sw + n * CC);
        float a = 0.f;
        #pragma unroll
        for (int q = 0; q < 8; q++) {
            float4 v = swr[q];
            a = fmaf(v.x, kr[4*q+0], a);
            a = fmaf(v.y, kr[4*q+1], a);
            a = fmaf(v.z, kr[4*q+2], a);
            a = fmaf(v.w, kr[4*q+3], a);
        }
        g_convw[((size_t)(n0 + n) * KK + k) * CC + d] = a;
    }
    for (int i = tid; i < 64 * KK * 2; i += 288) {
        int n = i / (KK * 2);
        int r = i - n * (KK * 2);
        int kk = r >> 1, j = r & 1;
        g_convpos[((n0 + n) * KK + kk) * 2 + j] = sp[n * 2 + j] + skp[kk * 2 + j];
    }
}

// ---------------- K2: main Kmat @ conv_w (f32x2 packed) ---------------------
// grid 288 = b(8) x nchunk(4) x msplit(9); 256 threads, one n per thread
__global__ void __launch_bounds__(256) k_main(const float* __restrict__ pos) {
    __shared__ __align__(16) float s_cw[MTILE * CC];   // 8 KB
    __shared__ float2 s_cp[MTILE];
    int blk = blockIdx.x;
    int b   = blk / 36;
    int rem = blk - b * 36;
    int nc  = rem / 9;
    int ms  = rem - nc * 9;
    int tid = threadIdx.x;
    int n = b * NBAT + nc * 256 + tid;
    float px = pos[2 * n + 0];
    float py = pos[2 * n + 1];
    unsigned long long acc[16];
    #pragma unroll
    for (int i = 0; i < 16; i++) acc[i] = 0ULL;
    const float C2 = -2.8853900817779268f;   // -2 * log2(e)

    int mbase = b * MM + ms * MCHUNK;
    for (int t = 0; t < NTILES; t++) {
        int m0 = mbase + t * MTILE;
        const float4* src = (const float4*)(g_convw + (size_t)m0 * CC);
        float4* dst = (float4*)s_cw;
        dst[tid]       = src[tid];
        dst[tid + 256] = src[tid + 256];
        if (tid < MTILE) s_cp[tid] = ((const float2*)g_convpos)[m0 + tid];
        __syncthreads();
        #pragma unroll 4
        for (int j = 0; j < MTILE; j++) {
            float2 cp = s_cp[j];
            float dx = px - cp.x, dy = py - cp.y;
            float d2 = fmaf(dy, dy, dx * dx);
            float w = ex2(C2 * d2);            // exp(-2*d2)
            unsigned long long w2 = pack2(w);
            const ulonglong2* cw = (const ulonglong2*)(s_cw + j * CC);
            #pragma unroll
            for (int q = 0; q < 8; q++) {
                ulonglong2 v = cw[q];
                ffma2(acc[2 * q + 0], w2, v.x);
                ffma2(acc[2 * q + 1], w2, v.y);
            }
        }
        __syncthreads();
    }
    ulonglong2* outp = (ulonglong2*)(g_part + ((size_t)ms * NTOT + n) * CC);
    #pragma unroll
    for (int q = 0; q < 8; q++)
        outp[q] = make_ulonglong2(acc[2 * q], acc[2 * q + 1]);
}

// ---------------- K3: sum partials, leaky, BN stats for x -------------------
// grid 128, 256 threads; 64 rows/block; tid = (rs=tid>>5, c=tid&31)
__global__ void k_x_stats() {
    __shared__ float red[256];
    int n0 = blockIdx.x * 64;
    int tid = threadIdx.x;
    int c = tid & 31, rs = tid >> 5;
    float sx = 0.f, sx2 = 0.f;
    #pragma unroll
    for (int i = 0; i < 8; i++) {
        int n = n0 + rs + 8 * i;
        size_t o = (size_t)n * CC + c;
        float v = 0.f;
        #pragma unroll
        for (int s = 0; s < MSPLIT; s++) v += g_part[(size_t)s * NTOT * CC + o];
        float x = v >= 0.f ? v : 0.01f * v;
        g_x[o] = x;
        sx += x; sx2 += x * x;
    }
    red[tid] = sx; __syncthreads();
    if (rs == 0) {
        float s = 0.f;
        #pragma unroll
        for (int j = 0; j < 8; j++) s += red[c + 32 * j];
        atomicAdd(&g_sx[c], s);
    }
    __syncthreads(); red[tid] = sx2; __syncthreads();
    if (rs == 0) {
        float s = 0.f;
        #pragma unroll
        for (int j = 0; j < 8; j++) s += red[c + 32 * j];
        atomicAdd(&g_sx2[c], s);
    }
}

// ---------------- K4: xn, h = leaky(xn@W1+b1), BN stats for h ---------------
// grid 256, 256 threads; 32 rows/block.  x-batchnorm scale computed inline.
__global__ void __launch_bounds__(256) k_h(const float* __restrict__ wts,
                                           const float* __restrict__ W1,
                                           const float* __restrict__ b1,
                                           const float* __restrict__ gamma,
                                           const float* __restrict__ beta) {
    __shared__ float sxn[32 * CC];      // 4 KB
    __shared__ float sW1[CC * CMID];    // 16 KB
    __shared__ float red[256];
    __shared__ float s_xs[CC], s_xh[CC];
    int n0 = blockIdx.x * 32;
    int tid = threadIdx.x;
    if (tid < CC) {
        float mu  = g_sx[tid] * (1.f / NTOT);
        float var = fmaf(-mu, mu, g_sx2[tid] * (1.f / NTOT));
        float rsv = rsqrtf(var + 1e-5f);
        float gs  = gamma[tid] * rsv;
        s_xs[tid] = gs;
        s_xh[tid] = fmaf(-gs, mu, beta[tid]);
    }
    #pragma unroll
    for (int i = 0; i < 16; i++) sW1[tid + 256 * i] = W1[tid + 256 * i];
    __syncthreads();
    #pragma unroll
    for (int i = 0; i < 4; i++) {
        int idx = tid + 256 * i;
        int r = idx >> 5, c = idx & 31;
        size_t o = (size_t)(n0 + r) * CC + c;
        float v = fmaf(s_xs[c], g_x[o], s_xh[c]) + wts[o];
        sxn[idx] = v;
        g_xn[o] = v;
    }
    __syncthreads();
    int c = tid & 127, rg = tid >> 7;  // rg 0..1
    float bc = b1[c];
    float sh = 0.f, sh2 = 0.f;
    for (int i = 0; i < 16; i++) {
        int r = rg + 2 * i;
        float a = bc;
        #pragma unroll
        for (int cin = 0; cin < CC; cin++)
            a = fmaf(sxn[r * CC + cin], sW1[cin * CMID + c], a);
        float h = a >= 0.f ? a : 0.01f * a;
        g_h[(size_t)(n0 + r) * CMID + c] = h;
        sh += h; sh2 += h * h;
    }
    red[tid] = sh; __syncthreads();
    if (rg == 0) atomicAdd(&g_sh[c], red[c] + red[c + 128]);
    __syncthreads(); red[tid] = sh2; __syncthreads();
    if (rg == 0) atomicAdd(&g_sh2[c], red[c] + red[c + 128]);
}

// ---------------- K5: mlp_out = hn@W2+b2, write both outputs ----------------
// grid 1024, 256 threads = 8 warps, one row per warp.  h-batchnorm inline.
__global__ void __launch_bounds__(256) k_final(const float* __restrict__ pos,
                                               const float* __restrict__ W2,
                                               const float* __restrict__ b2,
                                               const float* __restrict__ gamma,
                                               const float* __restrict__ beta,
                                               float* __restrict__ out) {
    __shared__ float sW2[CMID * 34];   // 17.4 KB
    __shared__ float sb2[34];
    __shared__ float shn[8][CMID];
    __shared__ float s_hs[CMID], s_hh[CMID];
    int tid = threadIdx.x;
    for (int i = tid; i < CMID * 34; i += 256) sW2[i] = W2[i];
    if (tid < 34) sb2[tid] = b2[tid];
    if (tid >= 64 && tid < 64 + CMID) {
        int c = tid - 64;
        float mu  = g_sh[c] * (1.f / NTOT);
        float var = fmaf(-mu, mu, g_sh2[c] * (1.f / NTOT));
        float rsv = rsqrtf(var + 1e-5f);
        float gs  = gamma[c] * rsv;
        s_hs[c] = gs;
        s_hh[c] = fmaf(-gs, mu, beta[c]);
    }
    __syncthreads();
    int w = tid >> 5, lane = tid & 31;
    int n = blockIdx.x * 8 + w;
    #pragma unroll
    for (int i = 0; i < 4; i++) {
        int cin = lane + 32 * i;
        float hv = g_h[(size_t)n * CMID + cin];
        shn[w][cin] = fmaf(s_hs[cin], hv, s_hh[cin]);
    }
    __syncwarp();
    float acc1 = sb2[lane];
    #pragma unroll 8
    for (int cin = 0; cin < CMID; cin++)
        acc1 = fmaf(shn[w][cin], sW2[cin * 34 + lane], acc1);
    float* out_pos = out;               // N*2
    float* out_w   = out + NTOT * 2;    // N*32
    if (lane < 2) {
        out_pos[n * 2 + lane] = pos[n * 2 + lane] + acc1;
        float acc2 = sb2[32 + lane];
        #pragma unroll 8
        for (int cin = 0; cin < CMID; cin++)
            acc2 = fmaf(shn[w][cin], sW2[cin * 34 + 32 + lane], acc2);
        out_w[n * CC + 30 + lane] = g_xn[(size_t)n * CC + 30 + lane] + acc2;
    } else {
        out_w[n * CC + lane - 2] = g_xn[(size_t)n * CC + lane - 2] + acc1;
    }
}

// ---------------- launch ----------------------------------------------------
extern "C" void kernel_launch(void* const* d_in, const int* in_sizes, int n_in,
                              void* d_out, int out_size) {
    const float* positions = (const float*)d_in[0];
    const float* weights   = (const float*)d_in[1];
    // d_in[2] = batch (all NB, unused; shapes are static)
    const float* kpos = (const float*)d_in[3];
    const float* kw   = (const float*)d_in[4];
    const float* cng  = (const float*)d_in[5];
    const float* cnb  = (const float*)d_in[6];
    const float* W1   = (const float*)d_in[7];
    const float* b1   = (const float*)d_in[8];
    const float* bng  = (const float*)d_in[9];
    const float* bnb  = (const float*)d_in[10];
    const float* W2   = (const float*)d_in[11];
    const float* b2   = (const float*)d_in[12];
    float* out = (float*)d_out;

    k_prep<<<128, 288>>>(positions, weights, kpos, kw);
    k_main<<<288, 256>>>(positions);
    k_x_stats<<<128, 256>>>();
    k_h<<<256, 256>>>(weights, W1, b1, cng, cnb);
    k_final<<<1024, 256>>>(positions, W2, b2, bng, bnb, out);
}

// round 4
// speedup vs baseline: 2.2221x; 1.7259x over previous
#include <cuda_runtime.h>
#include <cstdint>

#define NTOT 8192
#define BB   8
#define NBAT 1024
#define KK   9
#define CC   32
#define CMID 128
#define MM   9216        // NBAT*KK per batch
#define KSPLIT 8
#define KPART  1152      // MM / KSPLIT
#define NCH    36        // KPART / 32

// ---------------- scratch (device globals; no allocation anywhere) ----------
__device__ float  g_convwT[BB * CC * MM];   // [b][c][m], tf32-rounded
__device__ float4 g_abxy[BB * MM];          // (am, bx, by, 0) per m
__device__ float  g_part[KSPLIT * NTOT * CC];
__device__ float  g_x[NTOT * CC];
__device__ float  g_xn[NTOT * CC];
__device__ float  g_h[NTOT * CMID];
__device__ float  g_sx[CC], g_sx2[CC], g_sh[CMID], g_sh2[CMID];

// ---------------- helpers ----------------------------------------------------
__device__ __forceinline__ float ex2(float x) {
    float y; asm("ex2.approx.f32 %0, %1;" : "=f"(y) : "f"(x)); return y;
}
__device__ __forceinline__ float tf32r(float x) {   // rna round, keep as float
    uint32_t u; asm("cvt.rna.tf32.f32 %0, %1;" : "=r"(u) : "f"(x));
    return __uint_as_float(u);
}
__device__ __forceinline__ uint32_t tf32u(float x) { // rna round, raw bits
    uint32_t u; asm("cvt.rna.tf32.f32 %0, %1;" : "=r"(u) : "f"(x));
    return u;
}
__device__ __forceinline__ void mma_tf32(float* d, const uint32_t* a,
                                         uint32_t b0, uint32_t b1) {
    asm volatile(
        "mma.sync.aligned.m16n8k8.row.col.f32.tf32.tf32.f32 "
        "{%0,%1,%2,%3}, {%4,%5,%6,%7}, {%8,%9}, {%0,%1,%2,%3};"
        : "+f"(d[0]), "+f"(d[1]), "+f"(d[2]), "+f"(d[3])
        : "r"(a[0]), "r"(a[1]), "r"(a[2]), "r"(a[3]), "r"(b0), "r"(b1));
}

#define LOG2E 1.4426950408889634f
#define C2    (-2.0f * LOG2E)

// ---------------- K1: conv_w^T (tf32-rounded) + abxy + zero stats -----------
// grid 256 (32 n per block), 288 threads = (k=tid/32, d=tid%32)
__global__ void __launch_bounds__(288) k_prep(const float* __restrict__ pos,
                                              const float* __restrict__ wts,
                                              const float* __restrict__ kpos,
                                              const float* __restrict__ kw) {
    __shared__ __align__(16) float sw[32 * CC];      // 4 KB
    __shared__ float sp[64];
    __shared__ float skp[KK * 2];
    __shared__ __align__(16) float st[32 * KK * CC]; // 36.9 KB, m-major
    int tid = threadIdx.x;
    int n0 = blockIdx.x * 32;          // global n
    int b  = n0 >> 10;
    int m0 = (n0 & 1023) * KK;         // m within batch
    if (blockIdx.x == 0) {
        if (tid < CC)   { g_sx[tid] = 0.f; g_sx2[tid] = 0.f; }
        if (tid < CMID) { g_sh[tid] = 0.f; g_sh2[tid] = 0.f; }
    }
    for (int i = tid; i < 32 * CC; i += 288) sw[i] = wts[n0 * CC + i];
    if (tid < 64) sp[tid] = pos[n0 * 2 + tid];
    if (tid < KK * 2) skp[tid] = kpos[tid];
    int k = tid / 32, d = tid % 32;
    float kr[CC];
    #pragma unroll
    for (int c = 0; c < CC; c++) kr[c] = kw[(k * CC + c) * CC + d];
    __syncthreads();
    #pragma unroll 4
    for (int n = 0; n < 32; n++) {
        const float4* swr = (const float4*)(sw + n * CC);
        float a = 0.f;
        #pragma unroll
        for (int q = 0; q < 8; q++) {
            float4 v = swr[q];
            a = fmaf(v.x, kr[4*q+0], a);
            a = fmaf(v.y, kr[4*q+1], a);
            a = fmaf(v.z, kr[4*q+2], a);
            a = fmaf(v.w, kr[4*q+3], a);
        }
        st[(n * KK + k) * CC + d] = tf32r(a);
    }
    // abxy (288 m's, one per thread)
    {
        int n = tid / KK, kk = tid % KK;
        float cpx = sp[2 * n]     + skp[2 * kk];
        float cpy = sp[2 * n + 1] + skp[2 * kk + 1];
        float am  = C2 * fmaf(cpx, cpx, cpy * cpy);
        g_abxy[(size_t)b * MM + m0 + tid] =
            make_float4(am, 4.f * LOG2E * cpx, 4.f * LOG2E * cpy, 0.f);
    }
    __syncthreads();
    // transposed writeout: thread (c = tid/9, j = tid%9) writes 32 consecutive m
    {
        int c = tid / KK, j = tid % KK;
        float* dst = g_convwT + ((size_t)b * CC + c) * MM + m0 + j * 32;
        #pragma unroll 8
        for (int i = 0; i < 32; i++) dst[i] = st[(j * 32 + i) * CC + c];
    }
}

// ---------------- K2: Kmat @ conv_w via mma.sync tf32 -----------------------
// grid 128 = b(8) x rowblock(2) x ksplit(8); 256 threads = 8 warps,
// each warp owns a 64x32 output tile. A generated in registers.
__global__ void __launch_bounds__(256) k_main(const float* __restrict__ pos) {
    __shared__ float  sB[2][32 * 36];   // padded rows: bank-conflict-free frags
    __shared__ float4 sAB[2][32];
    int tid  = threadIdx.x;
    int w    = tid >> 5, lane = tid & 31;
    int g    = lane >> 2, tg = lane & 3;
    int blk  = blockIdx.x;
    int b  = blk >> 4;
    int rb = (blk >> 3) & 1;
    int ks = blk & 7;
    int ctabase = b * NBAT + rb * 512;
    size_t mbase = (size_t)b * MM + (size_t)ks * KPART;

    // staging mapping: thread -> (c = tid>>3, mq = tid&7), float4 per chunk
    int sc = tid >> 3, smq = tid & 7;
    const float4* gB  = (const float4*)(g_convwT + ((size_t)b * CC + sc) * MM
                                        + (size_t)ks * KPART) + smq;
    const float4* gAB = g_abxy + mbase;

    // per-lane row data: rows ctabase + w*64 + g + 8u, u = 0..7
    float px[8], py[8], pp[8];
    {
        int nr = ctabase + w * 64 + g;
        #pragma unroll
        for (int u = 0; u < 8; u++) {
            float2 p = ((const float2*)pos)[nr + 8 * u];
            px[u] = p.x; py[u] = p.y;
            pp[u] = C2 * fmaf(p.x, p.x, p.y * p.y);
        }
    }
    float acc[4][4][4];
    #pragma unroll
    for (int j = 0; j < 4; j++)
        #pragma unroll
        for (int i = 0; i < 4; i++)
            #pragma unroll
            for (int q = 0; q < 4; q++) acc[j][i][q] = 0.f;

    // stage chunk 0
    {
        float4 v = gB[0];
        float* d = &sB[0][sc * 36 + smq * 4];
        d[0] = v.x; d[1] = v.y; d[2] = v.z; d[3] = v.w;
        if (tid < 32) sAB[0][tid] = gAB[tid];
    }
    for (int t = 0; t < NCH; t++) {
        int buf = t & 1;
        __syncthreads();
        if (t + 1 < NCH) {
            float4 v = gB[(t + 1) * 8];
            float* d = &sB[buf ^ 1][sc * 36 + smq * 4];
            d[0] = v.x; d[1] = v.y; d[2] = v.z; d[3] = v.w;
            if (tid < 32) sAB[buf ^ 1][tid] = gAB[(t + 1) * 32 + tid];
        }
        #pragma unroll
        for (int s = 0; s < 4; s++) {
            int m0 = s * 8 + tg;
            float4 q0 = sAB[buf][m0];
            float4 q1 = sAB[buf][m0 + 4];
            uint32_t B0[4], B1[4];
            #pragma unroll
            for (int i = 0; i < 4; i++) {
                B0[i] = __float_as_uint(sB[buf][(g + 8 * i) * 36 + m0]);
                B1[i] = __float_as_uint(sB[buf][(g + 8 * i) * 36 + m0 + 4]);
            }
            uint32_t A[4][4];
            #pragma unroll
            for (int j = 0; j < 4; j++) {
                int u0 = 2 * j, u1 = 2 * j + 1;
                A[j][0] = tf32u(ex2(fmaf(q0.y, px[u0], fmaf(q0.z, py[u0], pp[u0] + q0.x))));
                A[j][1] = tf32u(ex2(fmaf(q0.y, px[u1], fmaf(q0.z, py[u1], pp[u1] + q0.x))));
                A[j][2] = tf32u(ex2(fmaf(q1.y, px[u0], fmaf(q1.z, py[u0], pp[u0] + q1.x))));
                A[j][3] = tf32u(ex2(fmaf(q1.y, px[u1], fmaf(q1.z, py[u1], pp[u1] + q1.x))));
            }
            #pragma unroll
            for (int j = 0; j < 4; j++)
                #pragma unroll
                for (int i = 0; i < 4; i++)
                    mma_tf32(acc[j][i], A[j], B0[i], B1[i]);
        }
    }
    // store: frag (j,i): rows ctabase+w*64+j*16+g (+8), cols i*8+tg*2 (+1)
    #pragma unroll
    for (int j = 0; j < 4; j++) {
        int nr0 = ctabase + w * 64 + j * 16 + g;
        #pragma unroll
        for (int i = 0; i < 4; i++) {
            int c = i * 8 + tg * 2;
            *(float2*)&g_part[((size_t)ks * NTOT + nr0) * CC + c] =
                make_float2(acc[j][i][0], acc[j][i][1]);
            *(float2*)&g_part[((size_t)ks * NTOT + nr0 + 8) * CC + c] =
                make_float2(acc[j][i][2], acc[j][i][3]);
        }
    }
}

// ---------------- K3: sum partials, leaky, BN stats for x -------------------
__global__ void k_x_stats() {
    __shared__ float red[256];
    int n0 = blockIdx.x * 64;
    int tid = threadIdx.x;
    int c = tid & 31, rs = tid >> 5;
    float sx = 0.f, sx2 = 0.f;
    #pragma unroll
    for (int i = 0; i < 8; i++) {
        int n = n0 + rs + 8 * i;
        size_t o = (size_t)n * CC + c;
        float v = 0.f;
        #pragma unroll
        for (int s = 0; s < KSPLIT; s++) v += g_part[(size_t)s * NTOT * CC + o];
        float x = v >= 0.f ? v : 0.01f * v;
        g_x[o] = x;
        sx += x; sx2 += x * x;
    }
    red[tid] = sx; __syncthreads();
    if (rs == 0) {
        float s = 0.f;
        #pragma unroll
        for (int j = 0; j < 8; j++) s += red[c + 32 * j];
        atomicAdd(&g_sx[c], s);
    }
    __syncthreads(); red[tid] = sx2; __syncthreads();
    if (rs == 0) {
        float s = 0.f;
        #pragma unroll
        for (int j = 0; j < 8; j++) s += red[c + 32 * j];
        atomicAdd(&g_sx2[c], s);
    }
}

// ---------------- K4: xn, h = leaky(xn@W1+b1), BN stats for h ---------------
__global__ void __launch_bounds__(256) k_h(const float* __restrict__ wts,
                                           const float* __restrict__ W1,
                                           const float* __restrict__ b1,
                                           const float* __restrict__ gamma,
                                           const float* __restrict__ beta) {
    __shared__ float sxn[32 * CC];
    __shared__ float sW1[CC * CMID];
    __shared__ float red[256];
    __shared__ float s_xs[CC], s_xh[CC];
    int n0 = blockIdx.x * 32;
    int tid = threadIdx.x;
    if (tid < CC) {
        float mu  = g_sx[tid] * (1.f / NTOT);
        float var = fmaf(-mu, mu, g_sx2[tid] * (1.f / NTOT));
        float rsv = rsqrtf(var + 1e-5f);
        float gs  = gamma[tid] * rsv;
        s_xs[tid] = gs;
        s_xh[tid] = fmaf(-gs, mu, beta[tid]);
    }
    #pragma unroll
    for (int i = 0; i < 16; i++) sW1[tid + 256 * i] = W1[tid + 256 * i];
    __syncthreads();
    #pragma unroll
    for (int i = 0; i < 4; i++) {
        int idx = tid + 256 * i;
        int rr = idx >> 5, c = idx & 31;
        size_t o = (size_t)(n0 + rr) * CC + c;
        float v = fmaf(s_xs[c], g_x[o], s_xh[c]) + wts[o];
        sxn[idx] = v;
        g_xn[o] = v;
    }
    __syncthreads();
    int c = tid & 127, rg = tid >> 7;
    float bc = b1[c];
    float sh = 0.f, sh2 = 0.f;
    for (int i = 0; i < 16; i++) {
        int rr = rg + 2 * i;
        float a = bc;
        #pragma unroll
        for (int cin = 0; cin < CC; cin++)
            a = fmaf(sxn[rr * CC + cin], sW1[cin * CMID + c], a);
        float hh = a >= 0.f ? a : 0.01f * a;
        g_h[(size_t)(n0 + rr) * CMID + c] = hh;
        sh += hh; sh2 += hh * hh;
    }
    red[tid] = sh; __syncthreads();
    if (rg == 0) atomicAdd(&g_sh[c], red[c] + red[c + 128]);
    __syncthreads(); red[tid] = sh2; __syncthreads();
    if (rg == 0) atomicAdd(&g_sh2[c], red[c] + red[c + 128]);
}

// ---------------- K5: mlp_out = hn@W2+b2, write both outputs ----------------
__global__ void __launch_bounds__(256) k_final(const float* __restrict__ pos,
                                               const float* __restrict__ W2,
                                               const float* __restrict__ b2,
                                               const float* __restrict__ gamma,
                                               const float* __restrict__ beta,
                                               float* __restrict__ out) {
    __shared__ float sW2[CMID * 34];
    __shared__ float sb2[34];
    __shared__ float shn[8][CMID];
    __shared__ float s_hs[CMID], s_hh[CMID];
    int tid = threadIdx.x;
    for (int i = tid; i < CMID * 34; i += 256) sW2[i] = W2[i];
    if (tid < 34) sb2[tid] = b2[tid];
    if (tid >= 64 && tid < 64 + CMID) {
        int c = tid - 64;
        float mu  = g_sh[c] * (1.f / NTOT);
        float var = fmaf(-mu, mu, g_sh2[c] * (1.f / NTOT));
        float rsv = rsqrtf(var + 1e-5f);
        float gs  = gamma[c] * rsv;
        s_hs[c] = gs;
        s_hh[c] = fmaf(-gs, mu, beta[c]);
    }
    __syncthreads();
    int w = tid >> 5, lane = tid & 31;
    int n = blockIdx.x * 8 + w;
    #pragma unroll
    for (int i = 0; i < 4; i++) {
        int cin = lane + 32 * i;
        float hv = g_h[(size_t)n * CMID + cin];
        shn[w][cin] = fmaf(s_hs[cin], hv, s_hh[cin]);
    }
    __syncwarp();
    float acc1 = sb2[lane];
    #pragma unroll 8
    for (int cin = 0; cin < CMID; cin++)
        acc1 = fmaf(shn[w][cin], sW2[cin * 34 + lane], acc1);
    float* out_pos = out;
    float* out_w   = out + NTOT * 2;
    if (lane < 2) {
        out_pos[n * 2 + lane] = pos[n * 2 + lane] + acc1;
        float acc2 = sb2[32 + lane];
        #pragma unroll 8
        for (int cin = 0; cin < CMID; cin++)
            acc2 = fmaf(shn[w][cin], sW2[cin * 34 + 32 + lane], acc2);
        out_w[n * CC + 30 + lane] = g_xn[(size_t)n * CC + 30 + lane] + acc2;
    } else {
        out_w[n * CC + lane - 2] = g_xn[(size_t)n * CC + lane - 2] + acc1;
    }
}

// ---------------- launch ----------------------------------------------------
extern "C" void kernel_launch(void* const* d_in, const int* in_sizes, int n_in,
                              void* d_out, int out_size) {
    const float* positions = (const float*)d_in[0];
    const float* weights   = (const float*)d_in[1];
    const float* kpos = (const float*)d_in[3];
    const float* kw   = (const float*)d_in[4];
    const float* cng  = (const float*)d_in[5];
    const float* cnb  = (const float*)d_in[6];
    const float* W1   = (const float*)d_in[7];
    const float* b1   = (const float*)d_in[8];
    const float* bng  = (const float*)d_in[9];
    const float* bnb  = (const float*)d_in[10];
    const float* W2   = (const float*)d_in[11];
    const float* b2   = (const float*)d_in[12];
    float* out = (float*)d_out;

    k_prep<<<256, 288>>>(positions, weights, kpos, kw);
    k_main<<<128, 256>>>(positions);
    k_x_stats<<<128, 256>>>();
    k_h<<<256, 256>>>(weights, W1, b1, cng, cnb);
    k_final<<<1024, 256>>>(positions, W2, b2, bng, bnb, out);
}

// round 5
// speedup vs baseline: 2.3427x; 1.0543x over previous
#include <cuda_runtime.h>
#include <cstdint>

#define NTOT 8192
#define BB   8
#define NBAT 1024
#define KK   9
#define CC   32
#define CMID 128
#define MM   9216        // NBAT*KK per batch
#define KSPLIT 9
#define KPART  1024      // MM / KSPLIT
#define NCH    32        // KPART / 32

// ---------------- scratch (device globals; no allocation anywhere) ----------
__device__ float  g_convwT[BB * CC * MM];   // [b][c][m], tf32-rounded
__device__ float4 g_abxy[BB * MM];          // (am, bx, by, 0) per m
__device__ float  g_part[KSPLIT * NTOT * CC];
__device__ float  g_x[NTOT * CC];
__device__ float  g_xn[NTOT * CC];
__device__ float  g_h[NTOT * CMID];
__device__ float  g_sx[CC], g_sx2[CC], g_sh[CMID], g_sh2[CMID];

// ---------------- helpers ----------------------------------------------------
__device__ __forceinline__ float ex2(float x) {
    float y; asm("ex2.approx.f32 %0, %1;" : "=f"(y) : "f"(x)); return y;
}
__device__ __forceinline__ float tf32r(float x) {   // rna round, keep as float
    uint32_t u; asm("cvt.rna.tf32.f32 %0, %1;" : "=r"(u) : "f"(x));
    return __uint_as_float(u);
}
__device__ __forceinline__ void mma_tf32(float* d, const uint32_t* a,
                                         uint32_t b0, uint32_t b1) {
    asm volatile(
        "mma.sync.aligned.m16n8k8.row.col.f32.tf32.tf32.f32 "
        "{%0,%1,%2,%3}, {%4,%5,%6,%7}, {%8,%9}, {%0,%1,%2,%3};"
        : "+f"(d[0]), "+f"(d[1]), "+f"(d[2]), "+f"(d[3])
        : "r"(a[0]), "r"(a[1]), "r"(a[2]), "r"(a[3]), "r"(b0), "r"(b1));
}

#define LOG2E 1.4426950408889634f
#define C2    (-2.0f * LOG2E)

// ---------------- K1: conv_w^T (tf32-rounded) + abxy + zero stats -----------
// grid 256 (32 n per block), 288 threads = (k=tid/32, d=tid%32)
__global__ void __launch_bounds__(288) k_prep(const float* __restrict__ pos,
                                              const float* __restrict__ wts,
                                              const float* __restrict__ kpos,
                                              const float* __restrict__ kw) {
    __shared__ __align__(16) float sw[32 * CC];      // 4 KB
    __shared__ float sp[64];
    __shared__ float skp[KK * 2];
    __shared__ __align__(16) float st[32 * KK * CC]; // 36.9 KB, m-major
    int tid = threadIdx.x;
    int n0 = blockIdx.x * 32;          // global n
    int b  = n0 >> 10;
    int m0 = (n0 & 1023) * KK;         // m within batch
    if (blockIdx.x == 0) {
        if (tid < CC)   { g_sx[tid] = 0.f; g_sx2[tid] = 0.f; }
        if (tid < CMID) { g_sh[tid] = 0.f; g_sh2[tid] = 0.f; }
    }
    for (int i = tid; i < 32 * CC; i += 288) sw[i] = wts[n0 * CC + i];
    if (tid < 64) sp[tid] = pos[n0 * 2 + tid];
    if (tid < KK * 2) skp[tid] = kpos[tid];
    int k = tid / 32, d = tid % 32;
    float kr[CC];
    #pragma unroll
    for (int c = 0; c < CC; c++) kr[c] = kw[(k * CC + c) * CC + d];
    __syncthreads();
    #pragma unroll 4
    for (int n = 0; n < 32; n++) {
        const float4* swr = (const float4*)(sw + n * CC);
        float a = 0.f;
        #pragma unroll
        for (int q = 0; q < 8; q++) {
            float4 v = swr[q];
            a = fmaf(v.x, kr[4*q+0], a);
            a = fmaf(v.y, kr[4*q+1], a);
            a = fmaf(v.z, kr[4*q+2], a);
            a = fmaf(v.w, kr[4*q+3], a);
        }
        st[(n * KK + k) * CC + d] = tf32r(a);
    }
    // abxy (288 m's, one per thread)
    {
        int n = tid / KK, kk = tid % KK;
        float cpx = sp[2 * n]     + skp[2 * kk];
        float cpy = sp[2 * n + 1] + skp[2 * kk + 1];
        float am  = C2 * fmaf(cpx, cpx, cpy * cpy);
        g_abxy[(size_t)b * MM + m0 + tid] =
            make_float4(am, 4.f * LOG2E * cpx, 4.f * LOG2E * cpy, 0.f);
    }
    __syncthreads();
    // transposed writeout: thread (c = tid/9, j = tid%9) writes 32 consecutive m
    {
        int c = tid / KK, j = tid % KK;
        float* dst = g_convwT + ((size_t)b * CC + c) * MM + m0 + j * 32;
        #pragma unroll 8
        for (int i = 0; i < 32; i++) dst[i] = st[(j * 32 + i) * CC + c];
    }
}

// ---------------- K2: Kmat @ conv_w via mma.sync tf32 -----------------------
// grid 144 = b(8) x rowblock(2) x ksplit(9); 256 threads = 8 warps,
// each warp owns a 64x32 output tile. A generated in registers (raw fp32 bits;
// HMMA truncates to tf32 in HW -> saves the cvt and shortens the dep chain).
__global__ void __launch_bounds__(256) k_main(const float* __restrict__ pos) {
    __shared__ float  sB[2][32 * 36];   // padded rows: bank-conflict-free frags
    __shared__ float4 sAB[2][32];
    int tid  = threadIdx.x;
    int w    = tid >> 5, lane = tid & 31;
    int g    = lane >> 2, tg = lane & 3;
    int blk  = blockIdx.x;
    int b   = blk / 18;
    int rem = blk - b * 18;
    int rb  = rem / 9;
    int ks  = rem - rb * 9;
    int ctabase = b * NBAT + rb * 512;
    size_t mbase = (size_t)b * MM + (size_t)ks * KPART;

    // staging mapping: thread -> (c = tid>>3, mq = tid&7), float4 per chunk
    int sc = tid >> 3, smq = tid & 7;
    const float4* gB  = (const float4*)(g_convwT + ((size_t)b * CC + sc) * MM
                                        + (size_t)ks * KPART) + smq;
    const float4* gAB = g_abxy + mbase;

    // per-lane row data: rows ctabase + w*64 + g + 8u, u = 0..7
    float px[8], py[8], pp[8];
    {
        int nr = ctabase + w * 64 + g;
        #pragma unroll
        for (int u = 0; u < 8; u++) {
            float2 p = ((const float2*)pos)[nr + 8 * u];
            px[u] = p.x; py[u] = p.y;
            pp[u] = C2 * fmaf(p.x, p.x, p.y * p.y);
        }
    }
    float acc[4][4][4];
    #pragma unroll
    for (int j = 0; j < 4; j++)
        #pragma unroll
        for (int i = 0; i < 4; i++)
            #pragma unroll
            for (int q = 0; q < 4; q++) acc[j][i][q] = 0.f;

    // stage chunk 0
    {
        float4 v = gB[0];
        float* d = &sB[0][sc * 36 + smq * 4];
        d[0] = v.x; d[1] = v.y; d[2] = v.z; d[3] = v.w;
        if (tid < 32) sAB[0][tid] = gAB[tid];
    }
    for (int t = 0; t < NCH; t++) {
        int buf = t & 1;
        __syncthreads();
        if (t + 1 < NCH) {
            float4 v = gB[(t + 1) * 8];
            float* d = &sB[buf ^ 1][sc * 36 + smq * 4];
            d[0] = v.x; d[1] = v.y; d[2] = v.z; d[3] = v.w;
            if (tid < 32) sAB[buf ^ 1][tid] = gAB[(t + 1) * 32 + tid];
        }
        #pragma unroll
        for (int s = 0; s < 4; s++) {
            int m0 = s * 8 + tg;
            float4 q0 = sAB[buf][m0];
            float4 q1 = sAB[buf][m0 + 4];
            uint32_t B0[4], B1[4];
            #pragma unroll
            for (int i = 0; i < 4; i++) {
                B0[i] = __float_as_uint(sB[buf][(g + 8 * i) * 36 + m0]);
                B1[i] = __float_as_uint(sB[buf][(g + 8 * i) * 36 + m0 + 4]);
            }
            uint32_t A[4][4];
            #pragma unroll
            for (int j = 0; j < 4; j++) {
                int u0 = 2 * j, u1 = 2 * j + 1;
                A[j][0] = __float_as_uint(ex2(fmaf(q0.y, px[u0], fmaf(q0.z, py[u0], pp[u0] + q0.x))));
                A[j][1] = __float_as_uint(ex2(fmaf(q0.y, px[u1], fmaf(q0.z, py[u1], pp[u1] + q0.x))));
                A[j][2] = __float_as_uint(ex2(fmaf(q1.y, px[u0], fmaf(q1.z, py[u0], pp[u0] + q1.x))));
                A[j][3] = __float_as_uint(ex2(fmaf(q1.y, px[u1], fmaf(q1.z, py[u1], pp[u1] + q1.x))));
            }
            #pragma unroll
            for (int j = 0; j < 4; j++)
                #pragma unroll
                for (int i = 0; i < 4; i++)
                    mma_tf32(acc[j][i], A[j], B0[i], B1[i]);
        }
    }
    // store: frag (j,i): rows ctabase+w*64+j*16+g (+8), cols i*8+tg*2 (+1)
    #pragma unroll
    for (int j = 0; j < 4; j++) {
        int nr0 = ctabase + w * 64 + j * 16 + g;
        #pragma unroll
        for (int i = 0; i < 4; i++) {
            int c = i * 8 + tg * 2;
            *(float2*)&g_part[((size_t)ks * NTOT + nr0) * CC + c] =
                make_float2(acc[j][i][0], acc[j][i][1]);
            *(float2*)&g_part[((size_t)ks * NTOT + nr0 + 8) * CC + c] =
                make_float2(acc[j][i][2], acc[j][i][3]);
        }
    }
}

// ---------------- K3: sum partials, leaky, BN stats for x -------------------
__global__ void k_x_stats() {
    __shared__ float red[256];
    int n0 = blockIdx.x * 64;
    int tid = threadIdx.x;
    int c = tid & 31, rs = tid >> 5;
    float sx = 0.f, sx2 = 0.f;
    #pragma unroll
    for (int i = 0; i < 8; i++) {
        int n = n0 + rs + 8 * i;
        size_t o = (size_t)n * CC + c;
        float v = 0.f;
        #pragma unroll
        for (int s = 0; s < KSPLIT; s++) v += g_part[(size_t)s * NTOT * CC + o];
        float x = v >= 0.f ? v : 0.01f * v;
        g_x[o] = x;
        sx += x; sx2 += x * x;
    }
    red[tid] = sx; __syncthreads();
    if (rs == 0) {
        float s = 0.f;
        #pragma unroll
        for (int j = 0; j < 8; j++) s += red[c + 32 * j];
        atomicAdd(&g_sx[c], s);
    }
    __syncthreads(); red[tid] = sx2; __syncthreads();
    if (rs == 0) {
        float s = 0.f;
        #pragma unroll
        for (int j = 0; j < 8; j++) s += red[c + 32 * j];
        atomicAdd(&g_sx2[c], s);
    }
}

// ---------------- K4: xn, h = leaky(xn@W1+b1), BN stats for h ---------------
// grid 128, 512 threads; 64 rows/block. x-batchnorm scale inline.
__global__ void __launch_bounds__(512) k_h(const float* __restrict__ wts,
                                           const float* __restrict__ W1,
                                           const float* __restrict__ b1,
                                           const float* __restrict__ gamma,
                                           const float* __restrict__ beta) {
    __shared__ float sxn[64 * CC];      // 8 KB
    __shared__ float sW1[CC * CMID];    // 16 KB
    __shared__ float red[512];
    __shared__ float s_xs[CC], s_xh[CC];
    int n0 = blockIdx.x * 64;
    int tid = threadIdx.x;
    if (tid < CC) {
        float mu  = g_sx[tid] * (1.f / NTOT);
        float var = fmaf(-mu, mu, g_sx2[tid] * (1.f / NTOT));
        float rsv = rsqrtf(var + 1e-5f);
        float gs  = gamma[tid] * rsv;
        s_xs[tid] = gs;
        s_xh[tid] = fmaf(-gs, mu, beta[tid]);
    }
    #pragma unroll
    for (int i = 0; i < 8; i++) sW1[tid + 512 * i] = W1[tid + 512 * i];
    __syncthreads();
    #pragma unroll
    for (int i = 0; i < 4; i++) {
        int idx = tid + 512 * i;
        int rr = idx >> 5, c = idx & 31;
        size_t o = (size_t)(n0 + rr) * CC + c;
        float v = fmaf(s_xs[c], g_x[o], s_xh[c]) + wts[o];
        sxn[idx] = v;
        g_xn[o] = v;
    }
    __syncthreads();
    int c = tid & 127, rg = tid >> 7;   // rg 0..3
    float bc = b1[c];
    float sh = 0.f, sh2 = 0.f;
    for (int i = 0; i < 16; i++) {
        int rr = rg + 4 * i;
        float a0 = bc, a1 = 0.f;        // two chains to break FMA latency
        #pragma unroll
        for (int cin = 0; cin < 16; cin++) {
            a0 = fmaf(sxn[rr * CC + cin],      sW1[cin * CMID + c],        a0);
            a1 = fmaf(sxn[rr * CC + cin + 16], sW1[(cin + 16) * CMID + c], a1);
        }
        float a = a0 + a1;
        float hh = a >= 0.f ? a : 0.01f * a;
        g_h[(size_t)(n0 + rr) * CMID + c] = hh;
        sh += hh; sh2 += hh * hh;
    }
    red[tid] = sh; __syncthreads();
    if (rg == 0) atomicAdd(&g_sh[c], red[c] + red[c + 128] + red[c + 256] + red[c + 384]);
    __syncthreads(); red[tid] = sh2; __syncthreads();
    if (rg == 0) atomicAdd(&g_sh2[c], red[c] + red[c + 128] + red[c + 256] + red[c + 384]);
}

// ---------------- K5: mlp_out = hn@W2+b2, write both outputs ----------------
// grid 256, 256 threads = 8 warps, 4 rows per warp. h-batchnorm inline.
__global__ void __launch_bounds__(256) k_final(const float* __restrict__ pos,
                                               const float* __restrict__ W2,
                                               const float* __restrict__ b2,
                                               const float* __restrict__ gamma,
                                               const float* __restrict__ beta,
                                               float* __restrict__ out) {
    __shared__ float sW2[CMID * 34];   // 17.4 KB
    __shared__ float sb2[34];
    __shared__ float shn[32][CMID];    // 16 KB
    __shared__ float s_hs[CMID], s_hh[CMID];
    int tid = threadIdx.x;
    for (int i = tid; i < CMID * 34; i += 256) sW2[i] = W2[i];
    if (tid < 34) sb2[tid] = b2[tid];
    if (tid >= 64 && tid < 64 + CMID) {
        int c = tid - 64;
        float mu  = g_sh[c] * (1.f / NTOT);
        float var = fmaf(-mu, mu, g_sh2[c] * (1.f / NTOT));
        float rsv = rsqrtf(var + 1e-5f);
        float gs  = gamma[c] * rsv;
        s_hs[c] = gs;
        s_hh[c] = fmaf(-gs, mu, beta[c]);
    }
    __syncthreads();
    int w = tid >> 5, lane = tid & 31;
    int nb = blockIdx.x * 32 + w * 4;
    #pragma unroll
    for (int r = 0; r < 4; r++)
        #pragma unroll
        for (int i = 0; i < 4; i++) {
            int cin = lane + 32 * i;
            float hv = g_h[(size_t)(nb + r) * CMID + cin];
            shn[w * 4 + r][cin] = fmaf(s_hs[cin], hv, s_hh[cin]);
        }
    __syncwarp();
    float* out_pos = out;
    float* out_w   = out + NTOT * 2;
    #pragma unroll
    for (int r = 0; r < 4; r++) {
        int n = nb + r;
        const float* hr = shn[w * 4 + r];
        float acc1 = sb2[lane];
        #pragma unroll 8
        for (int cin = 0; cin < CMID; cin++)
            acc1 = fmaf(hr[cin], sW2[cin * 34 + lane], acc1);
        if (lane < 2) {
            out_pos[n * 2 + lane] = pos[n * 2 + lane] + acc1;
            float acc2 = sb2[32 + lane];
            #pragma unroll 8
            for (int cin = 0; cin < CMID; cin++)
                acc2 = fmaf(hr[cin], sW2[cin * 34 + 32 + lane], acc2);
            out_w[n * CC + 30 + lane] = g_xn[(size_t)n * CC + 30 + lane] + acc2;
        } else {
            out_w[n * CC + lane - 2] = g_xn[(size_t)n * CC + lane - 2] + acc1;
        }
    }
}

// ---------------- launch ----------------------------------------------------
extern "C" void kernel_launch(void* const* d_in, const int* in_sizes, int n_in,
                              void* d_out, int out_size) {
    const float* positions = (const float*)d_in[0];
    const float* weights   = (const float*)d_in[1];
    const float* kpos = (const float*)d_in[3];
    const float* kw   = (const float*)d_in[4];
    const float* cng  = (const float*)d_in[5];
    const float* cnb  = (const float*)d_in[6];
    const float* W1   = (const float*)d_in[7];
    const float* b1   = (const float*)d_in[8];
    const float* bng  = (const float*)d_in[9];
    const float* bnb  = (const float*)d_in[10];
    const float* W2   = (const float*)d_in[11];
    const float* b2   = (const float*)d_in[12];
    float* out = (float*)d_out;

    k_prep<<<256, 288>>>(positions, weights, kpos, kw);
    k_main<<<144, 256>>>(positions);
    k_x_stats<<<128, 256>>>();
    k_h<<<128, 512>>>(weights, W1, b1, cng, cnb);
    k_final<<<256, 256>>>(positions, W2, b2, bng, bnb, out);
}

// round 6
// speedup vs baseline: 2.7770x; 1.1854x over previous
#include <cuda_runtime.h>
#include <cstdint>

#define NTOT 8192
#define BB   8
#define NBAT 1024
#define KK   9
#define CC   32
#define CMID 128
#define MM   9216        // NBAT*KK per batch
#define KSPLIT 9
#define KPART  1024      // MM / KSPLIT
#define NCH    32        // KPART / 32

// ---------------- scratch (device globals; no allocation anywhere) ----------
__device__ float  g_convwT[BB * CC * MM];   // [b][c][m], tf32-rounded
__device__ float4 g_abxy[BB * MM];          // (am, bx, by, 0) per m
__device__ float  g_part[KSPLIT * NTOT * CC];
__device__ float  g_x[NTOT * CC];
__device__ float  g_xn[NTOT * CC];
__device__ float  g_h[NTOT * CMID];
__device__ float  g_sx[CC], g_sx2[CC], g_sh[CMID], g_sh2[CMID];

// ---------------- helpers ----------------------------------------------------
__device__ __forceinline__ float ex2(float x) {
    float y; asm("ex2.approx.f32 %0, %1;" : "=f"(y) : "f"(x)); return y;
}
__device__ __forceinline__ float tf32r(float x) {   // rna round, keep as float
    uint32_t u; asm("cvt.rna.tf32.f32 %0, %1;" : "=r"(u) : "f"(x));
    return __uint_as_float(u);
}
__device__ __forceinline__ void mma_tf32(float* d, const uint32_t* a,
                                         uint32_t b0, uint32_t b1) {
    asm volatile(
        "mma.sync.aligned.m16n8k8.row.col.f32.tf32.tf32.f32 "
        "{%0,%1,%2,%3}, {%4,%5,%6,%7}, {%8,%9}, {%0,%1,%2,%3};"
        : "+f"(d[0]), "+f"(d[1]), "+f"(d[2]), "+f"(d[3])
        : "r"(a[0]), "r"(a[1]), "r"(a[2]), "r"(a[3]), "r"(b0), "r"(b1));
}

#define LOG2E 1.4426950408889634f
#define C2    (-2.0f * LOG2E)

// ---------------- K1: conv_w^T (tf32-rounded) + abxy + zero stats -----------
// grid 256 (32 n per block), 288 threads = (k=tid/32, d=tid%32)
// staging tile padded to stride 33 -> conflict-free transposed reads,
// writeout is warp-coalesced 128B stores.
__global__ void __launch_bounds__(288) k_prep(const float* __restrict__ pos,
                                              const float* __restrict__ wts,
                                              const float* __restrict__ kpos,
                                              const float* __restrict__ kw) {
    __shared__ __align__(16) float sw[32 * CC];       // 4 KB
    __shared__ float sp[64];
    __shared__ float skp[KK * 2];
    __shared__ float st[32 * KK * 33];                // 38 KB, [m_local][d] pad33
    int tid = threadIdx.x;
    int n0 = blockIdx.x * 32;          // global n
    int b  = n0 >> 10;
    int m0 = (n0 & 1023) * KK;         // m within batch
    if (blockIdx.x == 0) {
        if (tid < CC)   { g_sx[tid] = 0.f; g_sx2[tid] = 0.f; }
        if (tid < CMID) { g_sh[tid] = 0.f; g_sh2[tid] = 0.f; }
    }
    for (int i = tid; i < 32 * CC; i += 288) sw[i] = wts[n0 * CC + i];
    if (tid < 64) sp[tid] = pos[n0 * 2 + tid];
    if (tid < KK * 2) skp[tid] = kpos[tid];
    int k = tid / 32, d = tid % 32;
    float kr[CC];
    #pragma unroll
    for (int c = 0; c < CC; c++) kr[c] = kw[(k * CC + c) * CC + d];
    __syncthreads();
    #pragma unroll 4
    for (int n = 0; n < 32; n++) {
        const float4* swr = (const float4*)(sw + n * CC);
        float a = 0.f;
        #pragma unroll
        for (int q = 0; q < 8; q++) {
            float4 v = swr[q];
            a = fmaf(v.x, kr[4*q+0], a);
            a = fmaf(v.y, kr[4*q+1], a);
            a = fmaf(v.z, kr[4*q+2], a);
            a = fmaf(v.w, kr[4*q+3], a);
        }
        st[(n * KK + k) * 33 + d] = tf32r(a);
    }
    // abxy (288 m's, one per thread)
    {
        int n = tid / KK, kk = tid % KK;
        float cpx = sp[2 * n]     + skp[2 * kk];
        float cpy = sp[2 * n + 1] + skp[2 * kk + 1];
        float am  = C2 * fmaf(cpx, cpx, cpy * cpy);
        g_abxy[(size_t)b * MM + m0 + tid] =
            make_float4(am, 4.f * LOG2E * cpx, 4.f * LOG2E * cpy, 0.f);
    }
    __syncthreads();
    // transposed writeout: warp wi handles (c,j) pairs, lane covers 32 m's
    {
        int wi = tid >> 5, lane = tid & 31;
        for (int it = 0; it < 32; it++) {
            int cj = wi + 9 * it;        // 0..287
            int c = cj / KK, j = cj - c * KK;
            float v = st[(j * 32 + lane) * 33 + c];   // bank (lane+c)%32, CF
            g_convwT[((size_t)b * CC + c) * MM + m0 + j * 32 + lane] = v;
        }
    }
}

// ---------------- K2: Kmat @ conv_w via mma.sync tf32 -----------------------
// grid 144 = b(8) x rowblock(2) x ksplit(9); 512 threads = 16 warps,
// each warp owns a 32x32 output tile (4 warps/SMSP for latency hiding).
// A generated in registers (raw fp32 bits; HMMA truncates to tf32 in HW).
__global__ void __launch_bounds__(512) k_main(const float* __restrict__ pos) {
    __shared__ float  sB[2][32 * 36];   // padded rows: bank-conflict-free frags
    __shared__ float4 sAB[2][32];
    int tid  = threadIdx.x;
    int w    = tid >> 5, lane = tid & 31;
    int g    = lane >> 2, tg = lane & 3;
    int blk  = blockIdx.x;
    int b   = blk / 18;
    int rem = blk - b * 18;
    int rb  = rem / 9;
    int ks  = rem - rb * 9;
    int ctabase = b * NBAT + rb * 512;
    int rbase   = ctabase + w * 32;
    size_t mbase = (size_t)b * MM + (size_t)ks * KPART;

    // staging mapping: threads 0..255 -> (c = tid>>3, mq = tid&7), float4/chunk
    int sc = tid >> 3, smq = tid & 7;
    const float4* gB  = (const float4*)(g_convwT + ((size_t)b * CC + sc) * MM
                                        + (size_t)ks * KPART) + smq;
    const float4* gAB = g_abxy + mbase;

    // per-lane row data: rows rbase + g + 8u, u = 0..3
    float px[4], py[4], pp[4];
    #pragma unroll
    for (int u = 0; u < 4; u++) {
        float2 p = ((const float2*)pos)[rbase + g + 8 * u];
        px[u] = p.x; py[u] = p.y;
        pp[u] = C2 * fmaf(p.x, p.x, p.y * p.y);
    }
    float acc[2][4][4];
    #pragma unroll
    for (int j = 0; j < 2; j++)
        #pragma unroll
        for (int i = 0; i < 4; i++)
            #pragma unroll
            for (int q = 0; q < 4; q++) acc[j][i][q] = 0.f;

    // stage chunk 0
    if (tid < 256) {
        float4 v = gB[0];
        float* d = &sB[0][sc * 36 + smq * 4];
        d[0] = v.x; d[1] = v.y; d[2] = v.z; d[3] = v.w;
    }
    if (tid < 32) sAB[0][tid] = gAB[tid];
    for (int t = 0; t < NCH; t++) {
        int buf = t & 1;
        __syncthreads();
        if (t + 1 < NCH) {
            if (tid < 256) {
                float4 v = gB[(t + 1) * 8];
                float* d = &sB[buf ^ 1][sc * 36 + smq * 4];
                d[0] = v.x; d[1] = v.y; d[2] = v.z; d[3] = v.w;
            }
            if (tid < 32) sAB[buf ^ 1][tid] = gAB[(t + 1) * 32 + tid];
        }
        #pragma unroll
        for (int s = 0; s < 4; s++) {
            int m0 = s * 8 + tg;
            float4 q0 = sAB[buf][m0];
            float4 q1 = sAB[buf][m0 + 4];
            uint32_t B0[4], B1[4];
            #pragma unroll
            for (int i = 0; i < 4; i++) {
                B0[i] = __float_as_uint(sB[buf][(g + 8 * i) * 36 + m0]);
                B1[i] = __float_as_uint(sB[buf][(g + 8 * i) * 36 + m0 + 4]);
            }
            uint32_t A[2][4];
            #pragma unroll
            for (int j = 0; j < 2; j++) {
                int u0 = 2 * j, u1 = 2 * j + 1;
                A[j][0] = __float_as_uint(ex2(fmaf(q0.y, px[u0], fmaf(q0.z, py[u0], pp[u0] + q0.x))));
                A[j][1] = __float_as_uint(ex2(fmaf(q0.y, px[u1], fmaf(q0.z, py[u1], pp[u1] + q0.x))));
                A[j][2] = __float_as_uint(ex2(fmaf(q1.y, px[u0], fmaf(q1.z, py[u0], pp[u0] + q1.x))));
                A[j][3] = __float_as_uint(ex2(fmaf(q1.y, px[u1], fmaf(q1.z, py[u1], pp[u1] + q1.x))));
            }
            #pragma unroll
            for (int j = 0; j < 2; j++)
                #pragma unroll
                for (int i = 0; i < 4; i++)
                    mma_tf32(acc[j][i], A[j], B0[i], B1[i]);
        }
    }
    // store: frag (j,i): rows rbase+j*16+g (+8), cols i*8+tg*2 (+1)
    #pragma unroll
    for (int j = 0; j < 2; j++) {
        int nr0 = rbase + j * 16 + g;
        #pragma unroll
        for (int i = 0; i < 4; i++) {
            int c = i * 8 + tg * 2;
            *(float2*)&g_part[((size_t)ks * NTOT + nr0) * CC + c] =
                make_float2(acc[j][i][0], acc[j][i][1]);
            *(float2*)&g_part[((size_t)ks * NTOT + nr0 + 8) * CC + c] =
                make_float2(acc[j][i][2], acc[j][i][3]);
        }
    }
}

// ---------------- K3: sum partials, leaky, BN stats for x -------------------
// grid 256, 256 threads; 32 rows/block
__global__ void k_x_stats() {
    __shared__ float red[256];
    int n0 = blockIdx.x * 32;
    int tid = threadIdx.x;
    int c = tid & 31, rs = tid >> 5;
    float sx = 0.f, sx2 = 0.f;
    #pragma unroll
    for (int i = 0; i < 4; i++) {
        int n = n0 + rs + 8 * i;
        size_t o = (size_t)n * CC + c;
        float v = 0.f;
        #pragma unroll
        for (int s = 0; s < KSPLIT; s++) v += g_part[(size_t)s * NTOT * CC + o];
        float x = v >= 0.f ? v : 0.01f * v;
        g_x[o] = x;
        sx += x; sx2 += x * x;
    }
    red[tid] = sx; __syncthreads();
    if (rs == 0) {
        float s = 0.f;
        #pragma unroll
        for (int j = 0; j < 8; j++) s += red[c + 32 * j];
        atomicAdd(&g_sx[c], s);
    }
    __syncthreads(); red[tid] = sx2; __syncthreads();
    if (rs == 0) {
        float s = 0.f;
        #pragma unroll
        for (int j = 0; j < 8; j++) s += red[c + 32 * j];
        atomicAdd(&g_sx2[c], s);
    }
}

// ---------------- K4: xn, h = leaky(xn@W1+b1), BN stats for h ---------------
// grid 128, 512 threads; 64 rows/block. W1 column register-cached.
__global__ void __launch_bounds__(512) k_h(const float* __restrict__ wts,
                                           const float* __restrict__ W1,
                                           const float* __restrict__ b1,
                                           const float* __restrict__ gamma,
                                           const float* __restrict__ beta) {
    __shared__ float sxn[64 * CC];      // 8 KB
    __shared__ float sW1[CC * CMID];    // 16 KB
    __shared__ float red[512];
    __shared__ float s_xs[CC], s_xh[CC];
    int n0 = blockIdx.x * 64;
    int tid = threadIdx.x;
    if (tid < CC) {
        float mu  = g_sx[tid] * (1.f / NTOT);
        float var = fmaf(-mu, mu, g_sx2[tid] * (1.f / NTOT));
        float rsv = rsqrtf(var + 1e-5f);
        float gs  = gamma[tid] * rsv;
        s_xs[tid] = gs;
        s_xh[tid] = fmaf(-gs, mu, beta[tid]);
    }
    #pragma unroll
    for (int i = 0; i < 8; i++) sW1[tid + 512 * i] = W1[tid + 512 * i];
    __syncthreads();
    #pragma unroll
    for (int i = 0; i < 4; i++) {
        int idx = tid + 512 * i;
        int rr = idx >> 5, c = idx & 31;
        size_t o = (size_t)(n0 + rr) * CC + c;
        float v = fmaf(s_xs[c], g_x[o], s_xh[c]) + wts[o];
        sxn[idx] = v;
        g_xn[o] = v;
    }
    __syncthreads();
    int c = tid & 127, rg = tid >> 7;   // rg 0..3
    float wreg[CC];                     // register-cached W1 column
    #pragma unroll
    for (int cin = 0; cin < CC; cin++) wreg[cin] = sW1[cin * CMID + c];
    float bc = b1[c];
    float sh = 0.f, sh2 = 0.f;
    for (int i = 0; i < 16; i++) {
        int rr = rg + 4 * i;
        const float* xr = &sxn[rr * CC];
        float a0 = bc, a1 = 0.f;        // two chains to break FMA latency
        #pragma unroll
        for (int cin = 0; cin < 16; cin++) {
            a0 = fmaf(xr[cin],      wreg[cin],      a0);
            a1 = fmaf(xr[cin + 16], wreg[cin + 16], a1);
        }
        float a = a0 + a1;
        float hh = a >= 0.f ? a : 0.01f * a;
        g_h[(size_t)(n0 + rr) * CMID + c] = hh;
        sh += hh; sh2 += hh * hh;
    }
    red[tid] = sh; __syncthreads();
    if (rg == 0) atomicAdd(&g_sh[c], red[c] + red[c + 128] + red[c + 256] + red[c + 384]);
    __syncthreads(); red[tid] = sh2; __syncthreads();
    if (rg == 0) atomicAdd(&g_sh2[c], red[c] + red[c + 128] + red[c + 256] + red[c + 384]);
}

// ---------------- K5: mlp_out = hn@W2+b2, write both outputs ----------------
// grid 256, 256 threads = 8 warps, 4 rows per warp. h-batchnorm inline.
__global__ void __launch_bounds__(256) k_final(const float* __restrict__ pos,
                                               const float* __restrict__ W2,
                                               const float* __restrict__ b2,
                                               const float* __restrict__ gamma,
                                               const float* __restrict__ beta,
                                               float* __restrict__ out) {
    __shared__ float sW2[CMID * 34];   // 17.4 KB
    __shared__ float sb2[34];
    __shared__ float shn[32][CMID];    // 16 KB
    __shared__ float s_hs[CMID], s_hh[CMID];
    int tid = threadIdx.x;
    for (int i = tid; i < CMID * 34; i += 256) sW2[i] = W2[i];
    if (tid < 34) sb2[tid] = b2[tid];
    if (tid >= 64 && tid < 64 + CMID) {
        int c = tid - 64;
        float mu  = g_sh[c] * (1.f / NTOT);
        float var = fmaf(-mu, mu, g_sh2[c] * (1.f / NTOT));
        float rsv = rsqrtf(var + 1e-5f);
        float gs  = gamma[c] * rsv;
        s_hs[c] = gs;
        s_hh[c] = fmaf(-gs, mu, beta[c]);
    }
    __syncthreads();
    int w = tid >> 5, lane = tid & 31;
    int nb = blockIdx.x * 32 + w * 4;
    #pragma unroll
    for (int r = 0; r < 4; r++)
        #pragma unroll
        for (int i = 0; i < 4; i++) {
            int cin = lane + 32 * i;
            float hv = g_h[(size_t)(nb + r) * CMID + cin];
            shn[w * 4 + r][cin] = fmaf(s_hs[cin], hv, s_hh[cin]);
        }
    __syncwarp();
    float* out_pos = out;
    float* out_w   = out + NTOT * 2;
    #pragma unroll
    for (int r = 0; r < 4; r++) {
        int n = nb + r;
        const float* hr = shn[w * 4 + r];
        float acc1 = sb2[lane];
        #pragma unroll 8
        for (int cin = 0; cin < CMID; cin++)
            acc1 = fmaf(hr[cin], sW2[cin * 34 + lane], acc1);
        if (lane < 2) {
            out_pos[n * 2 + lane] = pos[n * 2 + lane] + acc1;
            float acc2 = sb2[32 + lane];
            #pragma unroll 8
            for (int cin = 0; cin < CMID; cin++)
                acc2 = fmaf(hr[cin], sW2[cin * 34 + 32 + lane], acc2);
            out_w[n * CC + 30 + lane] = g_xn[(size_t)n * CC + 30 + lane] + acc2;
        } else {
            out_w[n * CC + lane - 2] = g_xn[(size_t)n * CC + lane - 2] + acc1;
        }
    }
}

// ---------------- launch ----------------------------------------------------
extern "C" void kernel_launch(void* const* d_in, const int* in_sizes, int n_in,
                              void* d_out, int out_size) {
    const float* positions = (const float*)d_in[0];
    const float* weights   = (const float*)d_in[1];
    const float* kpos = (const float*)d_in[3];
    const float* kw   = (const float*)d_in[4];
    const float* cng  = (const float*)d_in[5];
    const float* cnb  = (const float*)d_in[6];
    const float* W1   = (const float*)d_in[7];
    const float* b1   = (const float*)d_in[8];
    const float* bng  = (const float*)d_in[9];
    const float* bnb  = (const float*)d_in[10];
    const float* W2   = (const float*)d_in[11];
    const float* b2   = (const float*)d_in[12];
    float* out = (float*)d_out;

    k_prep<<<256, 288>>>(positions, weights, kpos, kw);
    k_main<<<144, 512>>>(positions);
    k_x_stats<<<256, 256>>>();
    k_h<<<128, 512>>>(weights, W1, b1, cng, cnb);
    k_final<<<256, 256>>>(positions, W2, b2, bng, bnb, out);
}

// round 7
// speedup vs baseline: 2.9029x; 1.0453x over previous
#include <cuda_runtime.h>
#include <cstdint>

#define NTOT 8192
#define BB   8
#define NBAT 1024
#define KK   9
#define CC   32
#define CMID 128
#define MM   9216        // NBAT*KK per batch
#define KSPLIT 9
#define KPART  1024      // MM / KSPLIT
#define NCH    32        // KPART / 32
#define NGRP   16        // b(8) x rowblock(2)
#define HF_GRID 128

// ---------------- scratch (device globals; no allocation anywhere) ----------
__device__ float  g_convwT[BB * CC * MM];   // [b][c][m], tf32-rounded
__device__ float4 g_abxy[BB * MM];          // (am, bx, by, 0) per m
__device__ float  g_part[KSPLIT * NTOT * CC];
__device__ float  g_x[NTOT * CC];           // leaky(sampled)
__device__ float  g_sx[CC], g_sx2[CC], g_sh[CMID], g_sh2[CMID];
__device__ int    g_sync[NGRP];             // k_main group counters
__device__ int    g_cnt;                    // k_hf barrier counter

// ---------------- helpers ----------------------------------------------------
__device__ __forceinline__ float ex2(float x) {
    float y; asm("ex2.approx.f32 %0, %1;" : "=f"(y) : "f"(x)); return y;
}
__device__ __forceinline__ float tf32r(float x) {   // rna round, keep as float
    uint32_t u; asm("cvt.rna.tf32.f32 %0, %1;" : "=r"(u) : "f"(x));
    return __uint_as_float(u);
}
__device__ __forceinline__ void mma_tf32(float* d, const uint32_t* a,
                                         uint32_t b0, uint32_t b1) {
    asm volatile(
        "mma.sync.aligned.m16n8k8.row.col.f32.tf32.tf32.f32 "
        "{%0,%1,%2,%3}, {%4,%5,%6,%7}, {%8,%9}, {%0,%1,%2,%3};"
        : "+f"(d[0]), "+f"(d[1]), "+f"(d[2]), "+f"(d[3])
        : "r"(a[0]), "r"(a[1]), "r"(a[2]), "r"(a[3]), "r"(b0), "r"(b1));
}

#define LOG2E 1.4426950408889634f
#define C2    (-2.0f * LOG2E)

// ---------------- K1: conv_w^T (tf32-rounded) + abxy + zero counters --------
// grid 256 (32 n per block), 288 threads = (k=tid/32, d=tid%32)
__global__ void __launch_bounds__(288) k_prep(const float* __restrict__ pos,
                                              const float* __restrict__ wts,
                                              const float* __restrict__ kpos,
                                              const float* __restrict__ kw) {
    __shared__ __align__(16) float sw[32 * CC];       // 4 KB
    __shared__ float sp[64];
    __shared__ float skp[KK * 2];
    __shared__ float st[32 * KK * 33];                // 38 KB, [m_local][d] pad33
    int tid = threadIdx.x;
    int n0 = blockIdx.x * 32;          // global n
    int b  = n0 >> 10;
    int m0 = (n0 & 1023) * KK;         // m within batch
    if (blockIdx.x == 0) {             // re-zero per replay
        if (tid < CC)   { g_sx[tid] = 0.f; g_sx2[tid] = 0.f; }
        if (tid < CMID) { g_sh[tid] = 0.f; g_sh2[tid] = 0.f; }
        if (tid < NGRP) g_sync[tid] = 0;
        if (tid == NGRP) g_cnt = 0;
    }
    for (int i = tid; i < 32 * CC; i += 288) sw[i] = wts[n0 * CC + i];
    if (tid < 64) sp[tid] = pos[n0 * 2 + tid];
    if (tid < KK * 2) skp[tid] = kpos[tid];
    int k = tid / 32, d = tid % 32;
    float kr[CC];
    #pragma unroll
    for (int c = 0; c < CC; c++) kr[c] = kw[(k * CC + c) * CC + d];
    __syncthreads();
    #pragma unroll 4
    for (int n = 0; n < 32; n++) {
        const float4* swr = (const float4*)(sw + n * CC);
        float a = 0.f;
        #pragma unroll
        for (int q = 0; q < 8; q++) {
            float4 v = swr[q];
            a = fmaf(v.x, kr[4*q+0], a);
            a = fmaf(v.y, kr[4*q+1], a);
            a = fmaf(v.z, kr[4*q+2], a);
            a = fmaf(v.w, kr[4*q+3], a);
        }
        st[(n * KK + k) * 33 + d] = tf32r(a);
    }
    // abxy (288 m's, one per thread)
    {
        int n = tid / KK, kk = tid % KK;
        float cpx = sp[2 * n]     + skp[2 * kk];
        float cpy = sp[2 * n + 1] + skp[2 * kk + 1];
        float am  = C2 * fmaf(cpx, cpx, cpy * cpy);
        g_abxy[(size_t)b * MM + m0 + tid] =
            make_float4(am, 4.f * LOG2E * cpx, 4.f * LOG2E * cpy, 0.f);
    }
    __syncthreads();
    // transposed writeout: warp wi handles (c,j) pairs, lane covers 32 m's
    {
        int wi = tid >> 5, lane = tid & 31;
        for (int it = 0; it < 32; it++) {
            int cj = wi + 9 * it;        // 0..287
            int c = cj / KK, j = cj - c * KK;
            float v = st[(j * 32 + lane) * 33 + c];   // bank (lane+c)%32, CF
            g_convwT[((size_t)b * CC + c) * MM + m0 + j * 32 + lane] = v;
        }
    }
}

// ---------------- K2: Kmat @ conv_w via mma.sync tf32, fused reduction ------
// grid 144 = b(8) x rowblock(2) x ksplit(9); 512 threads = 16 warps.
// Last CTA of each (b,rb) group reduces the 9 partials, applies leaky,
// writes g_x and accumulates BN-x stats.
__global__ void __launch_bounds__(512) k_main(const float* __restrict__ pos) {
    __shared__ float  sB[2][32 * 36];   // padded rows: bank-conflict-free frags
    __shared__ float4 sAB[2][32];
    __shared__ float  red[512];
    __shared__ int    s_last;
    int tid  = threadIdx.x;
    int w    = tid >> 5, lane = tid & 31;
    int g    = lane >> 2, tg = lane & 3;
    int blk  = blockIdx.x;
    int b   = blk / 18;
    int rem = blk - b * 18;
    int rb  = rem / 9;
    int ks  = rem - rb * 9;
    int ctabase = b * NBAT + rb * 512;
    int rbase   = ctabase + w * 32;
    size_t mbase = (size_t)b * MM + (size_t)ks * KPART;

    // staging mapping: threads 0..255 -> (c = tid>>3, mq = tid&7), float4/chunk
    int sc = tid >> 3, smq = tid & 7;
    const float4* gB  = (const float4*)(g_convwT + ((size_t)b * CC + sc) * MM
                                        + (size_t)ks * KPART) + smq;
    const float4* gAB = g_abxy + mbase;

    // per-lane row data: rows rbase + g + 8u, u = 0..3
    float px[4], py[4], pp[4];
    #pragma unroll
    for (int u = 0; u < 4; u++) {
        float2 p = ((const float2*)pos)[rbase + g + 8 * u];
        px[u] = p.x; py[u] = p.y;
        pp[u] = C2 * fmaf(p.x, p.x, p.y * p.y);
    }
    float acc[2][4][4];
    #pragma unroll
    for (int j = 0; j < 2; j++)
        #pragma unroll
        for (int i = 0; i < 4; i++)
            #pragma unroll
            for (int q = 0; q < 4; q++) acc[j][i][q] = 0.f;

    // stage chunk 0
    if (tid < 256) {
        float4 v = gB[0];
        float* d = &sB[0][sc * 36 + smq * 4];
        d[0] = v.x; d[1] = v.y; d[2] = v.z; d[3] = v.w;
    }
    if (tid < 32) sAB[0][tid] = gAB[tid];
    for (int t = 0; t < NCH; t++) {
        int buf = t & 1;
        __syncthreads();
        if (t + 1 < NCH) {
            if (tid < 256) {
                float4 v = gB[(t + 1) * 8];
                float* d = &sB[buf ^ 1][sc * 36 + smq * 4];
                d[0] = v.x; d[1] = v.y; d[2] = v.z; d[3] = v.w;
            }
            if (tid < 32) sAB[buf ^ 1][tid] = gAB[(t + 1) * 32 + tid];
        }
        #pragma unroll
        for (int s = 0; s < 4; s++) {
            int m0 = s * 8 + tg;
            float4 q0 = sAB[buf][m0];
            float4 q1 = sAB[buf][m0 + 4];
            uint32_t B0[4], B1[4];
            #pragma unroll
            for (int i = 0; i < 4; i++) {
                B0[i] = __float_as_uint(sB[buf][(g + 8 * i) * 36 + m0]);
                B1[i] = __float_as_uint(sB[buf][(g + 8 * i) * 36 + m0 + 4]);
            }
            uint32_t A[2][4];
            #pragma unroll
            for (int j = 0; j < 2; j++) {
                int u0 = 2 * j, u1 = 2 * j + 1;
                A[j][0] = __float_as_uint(ex2(fmaf(q0.y, px[u0], fmaf(q0.z, py[u0], pp[u0] + q0.x))));
                A[j][1] = __float_as_uint(ex2(fmaf(q0.y, px[u1], fmaf(q0.z, py[u1], pp[u1] + q0.x))));
                A[j][2] = __float_as_uint(ex2(fmaf(q1.y, px[u0], fmaf(q1.z, py[u0], pp[u0] + q1.x))));
                A[j][3] = __float_as_uint(ex2(fmaf(q1.y, px[u1], fmaf(q1.z, py[u1], pp[u1] + q1.x))));
            }
            #pragma unroll
            for (int j = 0; j < 2; j++)
                #pragma unroll
                for (int i = 0; i < 4; i++)
                    mma_tf32(acc[j][i], A[j], B0[i], B1[i]);
        }
    }
    // store partials
    #pragma unroll
    for (int j = 0; j < 2; j++) {
        int nr0 = rbase + j * 16 + g;
        #pragma unroll
        for (int i = 0; i < 4; i++) {
            int c = i * 8 + tg * 2;
            *(float2*)&g_part[((size_t)ks * NTOT + nr0) * CC + c] =
                make_float2(acc[j][i][0], acc[j][i][1]);
            *(float2*)&g_part[((size_t)ks * NTOT + nr0 + 8) * CC + c] =
                make_float2(acc[j][i][2], acc[j][i][3]);
        }
    }
    // ---- group finish: last CTA reduces ----
    __threadfence();
    __syncthreads();
    if (tid == 0) s_last = (atomicAdd(&g_sync[b * 2 + rb], 1) == KSPLIT - 1);
    __syncthreads();
    if (!s_last) return;
    __threadfence();
    int c = tid & 31, rs = tid >> 5;    // rs 0..15
    float sx = 0.f, sx2 = 0.f;
    for (int i = 0; i < 32; i++) {
        int n = ctabase + i * 16 + rs;
        size_t o = (size_t)n * CC + c;
        float v = 0.f;
        #pragma unroll
        for (int s = 0; s < KSPLIT; s++) v += g_part[(size_t)s * NTOT * CC + o];
        float x = v >= 0.f ? v : 0.01f * v;
        g_x[o] = x;
        sx += x; sx2 += x * x;
    }
    red[tid] = sx; __syncthreads();
    if (rs == 0) {
        float s = 0.f;
        #pragma unroll
        for (int j = 0; j < 16; j++) s += red[c + 32 * j];
        atomicAdd(&g_sx[c], s);
    }
    __syncthreads(); red[tid] = sx2; __syncthreads();
    if (rs == 0) {
        float s = 0.f;
        #pragma unroll
        for (int j = 0; j < 16; j++) s += red[c + 32 * j];
        atomicAdd(&g_sx2[c], s);
    }
}

// ---------------- K3: fused  xn -> h -> BN(h) -> W2 -> outputs --------------
// grid 128, 512 threads; 64 rows/block; grid-wide spin barrier (all resident).
// dynamic smem layout (floats):
#define HF_SXN  0        // 64*32   = 2048
#define HF_SW1  2048     // 32*128  = 4096
#define HF_SH   6144     // 64*128  = 8192
#define HF_SW2  14336    // 128*34  = 4352
#define HF_SB2  18688    // 48
#define HF_SXS  18736    // 32
#define HF_SXH  18768    // 32
#define HF_SHS  18800    // 128
#define HF_SHH  18928    // 128
#define HF_RED  19056    // 512
#define HF_FLOATS 19568  // 78272 bytes

__global__ void __launch_bounds__(512) k_hf(const float* __restrict__ pos,
                                            const float* __restrict__ wts,
                                            const float* __restrict__ W1,
                                            const float* __restrict__ b1,
                                            const float* __restrict__ cng,
                                            const float* __restrict__ cnb,
                                            const float* __restrict__ bng,
                                            const float* __restrict__ bnb,
                                            const float* __restrict__ W2,
                                            const float* __restrict__ b2,
                                            float* __restrict__ out) {
    extern __shared__ float dyn[];
    float* sxn = dyn + HF_SXN;
    float* sW1 = dyn + HF_SW1;
    float* sh  = dyn + HF_SH;
    float* sW2 = dyn + HF_SW2;
    float* sb2 = dyn + HF_SB2;
    float* sxs = dyn + HF_SXS;
    float* sxh = dyn + HF_SXH;
    float* shs = dyn + HF_SHS;
    float* shh = dyn + HF_SHH;
    float* red = dyn + HF_RED;
    int tid = threadIdx.x;
    int n0 = blockIdx.x * 64;
    if (tid < CC) {
        float mu  = g_sx[tid] * (1.f / NTOT);
        float var = fmaf(-mu, mu, g_sx2[tid] * (1.f / NTOT));
        float rsv = rsqrtf(var + 1e-5f);
        float gs  = cng[tid] * rsv;
        sxs[tid] = gs;
        sxh[tid] = fmaf(-gs, mu, cnb[tid]);
    }
    #pragma unroll
    for (int i = 0; i < 8; i++) sW1[tid + 512 * i] = W1[tid + 512 * i];
    for (int i = tid; i < CMID * 34; i += 512) sW2[i] = W2[i];
    if (tid < 34) sb2[tid] = b2[tid];
    __syncthreads();
    #pragma unroll
    for (int i = 0; i < 4; i++) {
        int idx = tid + 512 * i;
        int rr = idx >> 5, c = idx & 31;
        size_t o = (size_t)(n0 + rr) * CC + c;
        sxn[idx] = fmaf(sxs[c], g_x[o], sxh[c]) + wts[o];
    }
    __syncthreads();
    // h = leaky(xn @ W1 + b1), kept in smem; accumulate stats
    int c = tid & 127, rg = tid >> 7;   // rg 0..3
    float wreg[CC];
    #pragma unroll
    for (int cin = 0; cin < CC; cin++) wreg[cin] = sW1[cin * CMID + c];
    float bc = b1[c];
    float shsum = 0.f, sh2sum = 0.f;
    for (int i = 0; i < 16; i++) {
        int rr = rg + 4 * i;
        const float4* xr4 = (const float4*)&sxn[rr * CC];
        float a0 = bc, a1 = 0.f;
        #pragma unroll
        for (int q = 0; q < 4; q++) {
            float4 v0 = xr4[q], v1 = xr4[q + 4];
            a0 = fmaf(v0.x, wreg[4*q+0],  a0);
            a1 = fmaf(v1.x, wreg[16+4*q+0], a1);
            a0 = fmaf(v0.y, wreg[4*q+1],  a0);
            a1 = fmaf(v1.y, wreg[16+4*q+1], a1);
            a0 = fmaf(v0.z, wreg[4*q+2],  a0);
            a1 = fmaf(v1.z, wreg[16+4*q+2], a1);
            a0 = fmaf(v0.w, wreg[4*q+3],  a0);
            a1 = fmaf(v1.w, wreg[16+4*q+3], a1);
        }
        float a = a0 + a1;
        float hh = a >= 0.f ? a : 0.01f * a;
        sh[rr * CMID + c] = hh;
        shsum += hh; sh2sum += hh * hh;
    }
    red[tid] = shsum; __syncthreads();
    if (rg == 0) atomicAdd(&g_sh[c], red[c] + red[c + 128] + red[c + 256] + red[c + 384]);
    __syncthreads(); red[tid] = sh2sum; __syncthreads();
    if (rg == 0) atomicAdd(&g_sh2[c], red[c] + red[c + 128] + red[c + 256] + red[c + 384]);
    // ---- grid-wide barrier (all 128 CTAs resident) ----
    __threadfence();
    __syncthreads();
    if (tid == 0) {
        atomicAdd(&g_cnt, 1);
        while (*(volatile int*)&g_cnt < HF_GRID) { }
    }
    __syncthreads();
    __threadfence();
    // h batchnorm scales, normalize sh in place
    if (tid < CMID) {
        float mu  = g_sh[tid] * (1.f / NTOT);
        float var = fmaf(-mu, mu, g_sh2[tid] * (1.f / NTOT));
        float rsv = rsqrtf(var + 1e-5f);
        float gs  = bng[tid] * rsv;
        shs[tid] = gs;
        shh[tid] = fmaf(-gs, mu, bnb[tid]);
    }
    __syncthreads();
    #pragma unroll
    for (int i = 0; i < 16; i++) {
        int idx = tid + 512 * i;
        int cc = idx & 127;
        sh[idx] = fmaf(shs[cc], sh[idx], shh[cc]);
    }
    __syncthreads();
    // mlp_out = hn @ W2 + b2, write both outputs
    int w = tid >> 5, lane = tid & 31;
    float* out_pos = out;
    float* out_w   = out + NTOT * 2;
    #pragma unroll
    for (int r = 0; r < 4; r++) {
        int lr = w * 4 + r;
        int n  = n0 + lr;
        const float* hr = &sh[lr * CMID];
        float acc1 = sb2[lane];
        #pragma unroll 8
        for (int cin = 0; cin < CMID; cin++)
            acc1 = fmaf(hr[cin], sW2[cin * 34 + lane], acc1);
        if (lane < 2) {
            out_pos[n * 2 + lane] = pos[n * 2 + lane] + acc1;
            float acc2 = sb2[32 + lane];
            #pragma unroll 8
            for (int cin = 0; cin < CMID; cin++)
                acc2 = fmaf(hr[cin], sW2[cin * 34 + 32 + lane], acc2);
            out_w[n * CC + 30 + lane] = sxn[lr * CC + 30 + lane] + acc2;
        } else {
            out_w[n * CC + lane - 2] = sxn[lr * CC + lane - 2] + acc1;
        }
    }
}

// ---------------- launch ----------------------------------------------------
extern "C" void kernel_launch(void* const* d_in, const int* in_sizes, int n_in,
                              void* d_out, int out_size) {
    const float* positions = (const float*)d_in[0];
    const float* weights   = (const float*)d_in[1];
    const float* kpos = (const float*)d_in[3];
    const float* kw   = (const float*)d_in[4];
    const float* cng  = (const float*)d_in[5];
    const float* cnb  = (const float*)d_in[6];
    const float* W1   = (const float*)d_in[7];
    const float* b1   = (const float*)d_in[8];
    const float* bng  = (const float*)d_in[9];
    const float* bnb  = (const float*)d_in[10];
    const float* W2   = (const float*)d_in[11];
    const float* b2   = (const float*)d_in[12];
    float* out = (float*)d_out;

    static int attr_done = 0;
    if (!attr_done) {
        cudaFuncSetAttribute(k_hf, cudaFuncAttributeMaxDynamicSharedMemorySize,
                             HF_FLOATS * 4);
        attr_done = 1;
    }
    k_prep<<<256, 288>>>(positions, weights, kpos, kw);
    k_main<<<144, 512>>>(positions);
    k_hf<<<HF_GRID, 512, HF_FLOATS * 4>>>(positions, weights, W1, b1,
                                          cng, cnb, bng, bnb, W2, b2, out);
}